// round 11
// baseline (speedup 1.0000x reference)
#include <cuda_runtime.h>
#include <cuda_fp16.h>
#include <cstdint>

#define S        4096
#define D_IN     128
#define H        4
#define D        32
#define HD       128
#define KSPLIT   4
#define KEYS_PER_SPLIT (S / KSPLIT)   // 1024
#define KT       128                   // keys per smem tile
#define QT       256                   // queries per attention block (8 warps * 32)
#define NEGBIG   1e30f
#define QSCALE   (0.17677669529663687f * 1.4426950408889634f)  // scale*log2e

#define V_CHSTR  264                   // dwords per 16-key V chunk (256 + 8 pad)
#define PROJ_SMEM ((128 * 64 + 64 * 64) * 4 + 512)

// ---------------- scratch (fp16x2 packed, 16 dwords per row) ----------------
__device__ uint32_t g_q[H * S * 16];        // permuted cols, pre-scaled by QSCALE
__device__ uint32_t g_k[H * S * 16];        // permuted cols
__device__ uint32_t g_v[H * S * 16];        // plain d-pair packing
__device__ float g_pl[H * S * KSPLIT];
__device__ float g_po[H * S * KSPLIT * D];

// ---------------- helpers ----------------------------------------------------
__device__ __forceinline__ float ex2(float x) {
    float r;
    asm("ex2.approx.f32 %0, %1;" : "=f"(r) : "f"(x));
    return r;
}
__device__ __forceinline__ uint32_t pack_h2(float lo, float hi) {
    __half2 h = __floats2half2_rn(lo, hi);       // x = lo bits, y = hi bits
    return *reinterpret_cast<uint32_t*>(&h);
}
__device__ __forceinline__ void mma16(float* d,
                                      uint32_t a0, uint32_t a1, uint32_t a2, uint32_t a3,
                                      uint32_t b0, uint32_t b1) {
    asm("mma.sync.aligned.m16n8k16.row.col.f32.f16.f16.f32 "
        "{%0,%1,%2,%3}, {%4,%5,%6,%7}, {%8,%9}, {%0,%1,%2,%3};"
        : "+f"(d[0]), "+f"(d[1]), "+f"(d[2]), "+f"(d[3])
        : "r"(a0), "r"(a1), "r"(a2), "r"(a3), "r"(b0), "r"(b1));
}
// group swizzle keyed on row (bit0 -> group bit2; bits1-2 -> group bits0-1)
__device__ __forceinline__ int swz3(int r) { return ((r & 1) << 2) | ((r >> 1) & 3); }

// ---------------- kernel 1: fp16 MMA QKV projection --------------------------
// grid (32 row-tiles, 3 proj, 2 n-halves) = 192 blocks; 256 threads = 8 warps.
// Block: 128 rows x 64 output cols. Warp w: rows w*16..+15, all 8 local n-blocks.
__global__ __launch_bounds__(256) void proj_kernel(
    const float* __restrict__ x,
    const float* __restrict__ Wq, const float* __restrict__ bq,
    const float* __restrict__ Wk, const float* __restrict__ bk,
    const float* __restrict__ Wv, const float* __restrict__ bv) {

    extern __shared__ uint32_t dsm[];
    uint32_t* sxh = dsm;                 // 128 rows x 64 pair-dwords (swizzled)
    uint32_t* swh = dsm + 128 * 64;      // W^T half: 64 n-rows x 64 k-pair dwords
    float*    sb  = (float*)(dsm + 128 * 64 + 64 * 64);   // 64 bias

    const int rowbase = blockIdx.x * 128;
    const int proj = blockIdx.y;
    const int nh   = blockIdx.z;         // n-half: cols nh*64 .. nh*64+63
    const float* W    = (proj == 0) ? Wq : (proj == 1) ? Wk : Wv;
    const float* bias = (proj == 0) ? bq : (proj == 1) ? bk : bv;
    uint32_t* out     = (proj == 0) ? g_q : (proj == 1) ? g_k : g_v;

    const int tid  = threadIdx.x;
    const int wid  = tid >> 5;
    const int lane = tid & 31;
    const int gid  = lane >> 2;
    const int tig  = lane & 3;

    // ---- fill x (fp32 -> fp16x2 pairs, swizzled): 32 pairs/thread ----
    #pragma unroll 8
    for (int i = 0; i < 32; i++) {
        int e = tid + (i << 8);          // 8192 pairs
        int row = e >> 6, p = e & 63;
        float2 xv = *(const float2*)(x + (size_t)(rowbase + row) * D_IN + 2 * p);
        sxh[row * 64 + ((((p & 7) ^ swz3(row)) << 3) | (p >> 3))] = pack_h2(xv.x, xv.y);
    }
    // ---- fill W^T half: swh[nL][pair p] = {W[2p][n], W[2p+1][n]} ----
    {
        int nL = tid & 63;
        int n  = nh * 64 + nL;
        int pb = (tid >> 6) << 4;        // 0,16,32,48
        #pragma unroll 4
        for (int i = 0; i < 16; i++) {
            int p = pb + i;
            float w0 = W[(size_t)(2 * p)     * HD + n];
            float w1 = W[(size_t)(2 * p + 1) * HD + n];
            swh[nL * 64 + ((((p & 7) ^ swz3(nL)) << 3) | (p >> 3))] = pack_h2(w0, w1);
        }
    }
    if (tid < 64) sb[tid] = bias[nh * 64 + tid];
    __syncthreads();

    // ---- A fragments (rows r0, r1 held for the 8 local n-blocks) ----
    const int r0 = (wid << 4) + gid;
    const int r1 = r0 + 8;
    uint32_t a0[8], a1[8], a2[8], a3[8];
    {
        const uint32_t* x0 = &sxh[r0 * 64];
        const uint32_t* x1 = &sxh[r1 * 64];
        int g0 = ((tig)     ^ swz3(r0)) << 3;
        int g2 = ((tig + 4) ^ swz3(r0)) << 3;
        int h0 = ((tig)     ^ swz3(r1)) << 3;
        int h2 = ((tig + 4) ^ swz3(r1)) << 3;
        *(uint4*)&a0[0] = *(const uint4*)&x0[g0]; *(uint4*)&a0[4] = *(const uint4*)&x0[g0 + 4];
        *(uint4*)&a2[0] = *(const uint4*)&x0[g2]; *(uint4*)&a2[4] = *(const uint4*)&x0[g2 + 4];
        *(uint4*)&a1[0] = *(const uint4*)&x1[h0]; *(uint4*)&a1[4] = *(const uint4*)&x1[h0 + 4];
        *(uint4*)&a3[0] = *(const uint4*)&x1[h2]; *(uint4*)&a3[4] = *(const uint4*)&x1[h2 + 4];
    }

    const float oscale = (proj == 0) ? QSCALE : 1.0f;
    const bool permute = (proj != 2);

    // ---- 8 local n-blocks, 2 at a time for MMA ILP ----
    #pragma unroll 1
    for (int nb2 = 0; nb2 < 4; nb2++) {
        const int nbA = 2 * nb2, nbB = 2 * nb2 + 1;     // local n-blocks
        const int nA = nbA * 8 + gid, nB = nbB * 8 + gid;  // local n-rows

        uint32_t b0A[8], b1A[8], b0B[8], b1B[8];
        {
            const uint32_t* wA = &swh[nA * 64];
            int ga = ((tig)     ^ swz3(nA)) << 3;
            int gb = ((tig + 4) ^ swz3(nA)) << 3;
            *(uint4*)&b0A[0] = *(const uint4*)&wA[ga]; *(uint4*)&b0A[4] = *(const uint4*)&wA[ga + 4];
            *(uint4*)&b1A[0] = *(const uint4*)&wA[gb]; *(uint4*)&b1A[4] = *(const uint4*)&wA[gb + 4];
            const uint32_t* wB = &swh[nB * 64];
            int gc = ((tig)     ^ swz3(nB)) << 3;
            int gd = ((tig + 4) ^ swz3(nB)) << 3;
            *(uint4*)&b0B[0] = *(const uint4*)&wB[gc]; *(uint4*)&b0B[4] = *(const uint4*)&wB[gc + 4];
            *(uint4*)&b1B[0] = *(const uint4*)&wB[gd]; *(uint4*)&b1B[4] = *(const uint4*)&wB[gd + 4];
        }

        float cA[4] = {0.f, 0.f, 0.f, 0.f};
        float cB[4] = {0.f, 0.f, 0.f, 0.f};
        #pragma unroll
        for (int ks = 0; ks < 8; ks++) {
            mma16(cA, a0[ks], a1[ks], a2[ks], a3[ks], b0A[ks], b1A[ks]);
            mma16(cB, a0[ks], a1[ks], a2[ks], a3[ks], b0B[ks], b1B[ks]);
        }

        // ---- epilogue for both n-blocks ----
        #pragma unroll
        for (int s = 0; s < 2; s++) {
            const float* c = s ? cB : cA;
            const int nbl = s ? nbB : nbA;
            const int col0L = 8 * nbl + 2 * tig;        // local col in half
            const int col0  = nh * 64 + col0L;          // global col
            float v0 = (c[0] + sb[col0L])     * oscale;   // row r0
            float v1 = (c[1] + sb[col0L + 1]) * oscale;
            float v2 = (c[2] + sb[col0L])     * oscale;   // row r1
            float v3 = (c[3] + sb[col0L + 1]) * oscale;
            int h0 = col0 >> 5;
            int d2 = (col0 >> 1) & 15;
            int p  = permute ? (((d2 & 3) << 2) | (d2 >> 2)) : d2;
            out[((size_t)h0 * S + rowbase + r0) * 16 + p] = pack_h2(v0, v1);
            out[((size_t)h0 * S + rowbase + r1) * 16 + p] = pack_h2(v2, v3);
        }
    }
}

// ---------------- kernel 2: fp16 m16n8k16 flash attention -------------------
// grid (16, H, 4) = 256 blocks; 256 threads = 8 warps; 32 queries per warp.
__global__ __launch_bounds__(256, 2) void attn_kernel(const int* __restrict__ mask) {
    const int qtile = blockIdx.x;
    const int h     = blockIdx.y;
    const int kc    = blockIdx.z;
    const int tid   = threadIdx.x;
    const int warp  = tid >> 5;
    const int lane  = tid & 31;
    const int gid   = lane >> 2;
    const int tig   = lane & 3;

    __shared__ __align__(16) uint32_t sk[KT * 16];             // 8 KB (permuted fp16x2)
    __shared__ __align__(16) uint32_t sv[(KT / 16) * V_CHSTR]; // 8.25 KB
    __shared__ float sbias[KT];
    __shared__ int smask[64];

    if (tid < 64) smask[tid] = mask[tid];

    const int qbase = qtile * QT + warp * 32;

    uint4 qlo[2], qhi[2];
    #pragma unroll
    for (int t = 0; t < 2; t++) {
        const uint32_t* qr = g_q + ((size_t)(h * S) + qbase + t * 16 + gid) * 16;
        qlo[t] = *(const uint4*)(qr + 4 * tig);
        qhi[t] = *(const uint4*)(qr + 8 * 16 + 4 * tig);
    }

    float o[2][4][4];
    #pragma unroll
    for (int t = 0; t < 2; t++)
        #pragma unroll
        for (int nc = 0; nc < 4; nc++)
            #pragma unroll
            for (int r = 0; r < 4; r++) o[t][nc][r] = 0.0f;
    float l[2][2] = {{0.f, 0.f}, {0.f, 0.f}};

    const int kbase = kc * KEYS_PER_SPLIT;
    const float2* sb2 = (const float2*)sbias;

    const int vkey2 = tid & 63;
    const int vdb   = tid >> 6;
    const int vch   = vkey2 >> 3;
    const int vkc2  = vkey2 & 7;
    const int vwoff = vch * V_CHSTR + 64 * vdb + 2 * (vkc2 & 3) + (vkc2 >> 2);

    for (int jt = 0; jt < KEYS_PER_SPLIT / KT; jt++) {   // 8 tiles
        __syncthreads();
        {
            const uint4* kg4 = (const uint4*)(g_k + ((size_t)(h * S) + kbase + jt * KT) * 16);
            ((uint4*)sk)[tid]       = kg4[tid];
            ((uint4*)sk)[tid + 256] = kg4[tid + 256];

            const uint4* vg4 = (const uint4*)(g_v + ((size_t)(h * S) + kbase + jt * KT) * 16);
            uint4 e4 = vg4[(2 * vkey2) * 4 + vdb];
            uint4 o4 = vg4[(2 * vkey2) * 4 + 4 + vdb];
            uint32_t* dst = &sv[vwoff];
            dst[0]  = __byte_perm(e4.x, o4.x, 0x5410);
            dst[8]  = __byte_perm(e4.x, o4.x, 0x7632);
            dst[16] = __byte_perm(e4.y, o4.y, 0x5410);
            dst[24] = __byte_perm(e4.y, o4.y, 0x7632);
            dst[32] = __byte_perm(e4.z, o4.z, 0x5410);
            dst[40] = __byte_perm(e4.z, o4.z, 0x7632);
            dst[48] = __byte_perm(e4.w, o4.w, 0x5410);
            dst[56] = __byte_perm(e4.w, o4.w, 0x7632);

            if (tid < KT) {
                int key = kbase + jt * KT + tid;
                sbias[tid] = (smask[key >> 6] && smask[key & 63]) ? 0.0f : -NEGBIG;
            }
        }
        __syncthreads();

        #pragma unroll 1
        for (int kg = 0; kg < KT / 16; kg++) {     // 8 chunks of 16 keys
            const uint4 kb0 = *(const uint4*)&sk[(kg * 16 + gid) * 16 + 4 * tig];
            const uint4 kb1 = *(const uint4*)&sk[(kg * 16 + 8 + gid) * 16 + 4 * tig];

            float c[2][2][4];
            #pragma unroll
            for (int t = 0; t < 2; t++) {
                #pragma unroll
                for (int g = 0; g < 2; g++)
                    c[t][g][0] = c[t][g][1] = c[t][g][2] = c[t][g][3] = 0.0f;
                mma16(c[t][0], qlo[t].x, qhi[t].x, qlo[t].y, qhi[t].y, kb0.x, kb0.y);
                mma16(c[t][0], qlo[t].z, qhi[t].z, qlo[t].w, qhi[t].w, kb0.z, kb0.w);
                mma16(c[t][1], qlo[t].x, qhi[t].x, qlo[t].y, qhi[t].y, kb1.x, kb1.y);
                mma16(c[t][1], qlo[t].z, qhi[t].z, qlo[t].w, qhi[t].w, kb1.z, kb1.w);
            }

            float2 bg0 = sb2[kg * 8 + tig];
            float2 bg1 = sb2[kg * 8 + 4 + tig];

            uint32_t pa[2][4];
            #pragma unroll
            for (int t = 0; t < 2; t++) {
                float p00 = ex2(c[t][0][0] + bg0.x), p01 = ex2(c[t][0][1] + bg0.y);
                float p02 = ex2(c[t][0][2] + bg0.x), p03 = ex2(c[t][0][3] + bg0.y);
                float p10 = ex2(c[t][1][0] + bg1.x), p11 = ex2(c[t][1][1] + bg1.y);
                float p12 = ex2(c[t][1][2] + bg1.x), p13 = ex2(c[t][1][3] + bg1.y);
                l[t][0] += (p00 + p01) + (p10 + p11);
                l[t][1] += (p02 + p03) + (p12 + p13);
                pa[t][0] = pack_h2(p00, p01);
                pa[t][1] = pack_h2(p02, p03);
                pa[t][2] = pack_h2(p10, p11);
                pa[t][3] = pack_h2(p12, p13);
            }

            const uint32_t* vb = &sv[kg * V_CHSTR + 8 * gid + 2 * tig];
            #pragma unroll
            for (int nc = 0; nc < 4; nc++) {
                uint2 vv = *(const uint2*)(vb + 64 * nc);
                mma16(o[0][nc], pa[0][0], pa[0][1], pa[0][2], pa[0][3], vv.x, vv.y);
                mma16(o[1][nc], pa[1][0], pa[1][1], pa[1][2], pa[1][3], vv.x, vv.y);
            }
        }
    }

    // ---- reduce l within groups; write partials ----
    const unsigned FULL = 0xffffffffu;
    #pragma unroll
    for (int t = 0; t < 2; t++) {
        float l0 = l[t][0], l1 = l[t][1];
        l0 += __shfl_xor_sync(FULL, l0, 1); l0 += __shfl_xor_sync(FULL, l0, 2);
        l1 += __shfl_xor_sync(FULL, l1, 1); l1 += __shfl_xor_sync(FULL, l1, 2);

        const int q0 = qbase + t * 16 + gid;
        const int q1 = q0 + 8;
        const int prow0 = ((h * S) + q0) * KSPLIT + kc;
        const int prow1 = ((h * S) + q1) * KSPLIT + kc;
        if (tig == 0) { g_pl[prow0] = l0; g_pl[prow1] = l1; }

        float2* po0 = (float2*)(g_po + (size_t)prow0 * D);
        float2* po1 = (float2*)(g_po + (size_t)prow1 * D);
        #pragma unroll
        for (int nc = 0; nc < 4; nc++) {
            po0[nc * 4 + tig] = make_float2(o[t][nc][0], o[t][nc][1]);
            po1[nc * 4 + tig] = make_float2(o[t][nc][2], o[t][nc][3]);
        }
    }
}

// ---------------- kernel 3: combine split-K + sum-pool over j (float4) ------
// grid (64, H); 256 threads: q = tid&7 (d-quad), g = tid>>3 (j mod 32).
__global__ __launch_bounds__(256) void reduce_kernel(float* __restrict__ out) {
    const int i = blockIdx.x;
    const int h = blockIdx.y;
    const int tid = threadIdx.x;
    const int q = tid & 7;
    const int g = tid >> 3;

    __shared__ float sinvL[64];
    __shared__ float4 sacc[256];
    __shared__ float4 sp[64];

    if (tid < 64) {
        int s = i * 64 + tid;
        int base = (h * S + s) * KSPLIT;
        float L = 0.0f;
        #pragma unroll
        for (int k = 0; k < KSPLIT; k++) L += g_pl[base + k];
        sinvL[tid] = 1.0f / L;
    }
    __syncthreads();

    float4 acc = make_float4(0.f, 0.f, 0.f, 0.f);
    #pragma unroll
    for (int jj = 0; jj < 2; jj++) {
        int j = g + 32 * jj;
        int s = i * 64 + j;
        const float4* po4 = (const float4*)(g_po + ((size_t)(h * S + s) * KSPLIT) * D) + q;
        float4 v0 = po4[0];
        float4 v1 = po4[8];     // kc=1: +D floats = +8 float4
        float4 v2 = po4[16];
        float4 v3 = po4[24];
        float w = sinvL[j];
        acc.x += w * (v0.x + v1.x + v2.x + v3.x);
        acc.y += w * (v0.y + v1.y + v2.y + v3.y);
        acc.z += w * (v0.z + v1.z + v2.z + v3.z);
        acc.w += w * (v0.w + v1.w + v2.w + v3.w);
    }

    sacc[tid] = acc;
    __syncthreads();
    if (tid < 64) {
        const int qq = tid >> 3, g8 = tid & 7;
        float4 r = make_float4(0.f, 0.f, 0.f, 0.f);
        #pragma unroll
        for (int m = 0; m < 4; m++) {
            float4 v = sacc[(g8 * 4 + m) * 8 + qq];
            r.x += v.x; r.y += v.y; r.z += v.z; r.w += v.w;
        }
        sp[g8 * 8 + qq] = r;
    }
    __syncthreads();
    if (tid < 8) {
        float4 r = make_float4(0.f, 0.f, 0.f, 0.f);
        #pragma unroll
        for (int g8 = 0; g8 < 8; g8++) {
            float4 v = sp[g8 * 8 + tid];
            r.x += v.x; r.y += v.y; r.z += v.z; r.w += v.w;
        }
        *(float4*)(out + i * HD + h * 32 + tid * 4) = r;
    }
}

// ---------------- launch ----------------------------------------------------
extern "C" void kernel_launch(void* const* d_in, const int* in_sizes, int n_in,
                              void* d_out, int out_size) {
    const float* x    = (const float*)d_in[0];
    const int*   mask = (const int*)  d_in[1];
    const float* Wq   = (const float*)d_in[2];
    const float* bq   = (const float*)d_in[3];
    const float* Wk   = (const float*)d_in[4];
    const float* bk   = (const float*)d_in[5];
    const float* Wv   = (const float*)d_in[6];
    const float* bv   = (const float*)d_in[7];
    float* out = (float*)d_out;

    cudaFuncSetAttribute(proj_kernel, cudaFuncAttributeMaxDynamicSharedMemorySize, PROJ_SMEM);
    proj_kernel<<<dim3(32, 3, 2), 256, PROJ_SMEM>>>(x, Wq, bq, Wk, bk, Wv, bv);
    attn_kernel<<<dim3(S / QT, H, KSPLIT), 256>>>(mask);
    reduce_kernel<<<dim3(64, H), 256>>>(out);
}

// round 12
// speedup vs baseline: 1.4875x; 1.4875x over previous
#include <cuda_runtime.h>
#include <cuda_fp16.h>
#include <cstdint>

#define S        4096
#define D_IN     128
#define H        4
#define D        32
#define HD       128
#define KSPLIT   4
#define KEYS_PER_SPLIT (S / KSPLIT)   // 1024
#define KT       128                   // keys per smem tile
#define QT       256                   // queries per attention block (8 warps * 32)
#define NEGBIG   1e30f
#define QSCALE   (0.17677669529663687f * 1.4426950408889634f)  // scale*log2e

#define V_CHSTR  264                   // dwords per 16-key V chunk (256 + 8 pad)
#define PROJ_SMEM ((2 * 128 * 64) * 4 + 512)

// ---------------- scratch (fp16x2 packed, 16 dwords per row) ----------------
__device__ uint32_t g_q[H * S * 16];        // permuted cols, pre-scaled by QSCALE
__device__ uint32_t g_k[H * S * 16];        // permuted cols
__device__ uint32_t g_v[H * S * 16];        // plain d-pair packing
__device__ float g_pl[H * S * KSPLIT];
__device__ float g_po[H * S * KSPLIT * D];

// ---------------- helpers ----------------------------------------------------
__device__ __forceinline__ float ex2(float x) {
    float r;
    asm("ex2.approx.f32 %0, %1;" : "=f"(r) : "f"(x));
    return r;
}
__device__ __forceinline__ uint32_t pack_h2(float lo, float hi) {
    __half2 h = __floats2half2_rn(lo, hi);       // x = lo bits, y = hi bits
    return *reinterpret_cast<uint32_t*>(&h);
}
__device__ __forceinline__ void mma16(float* d,
                                      uint32_t a0, uint32_t a1, uint32_t a2, uint32_t a3,
                                      uint32_t b0, uint32_t b1) {
    asm("mma.sync.aligned.m16n8k16.row.col.f32.f16.f16.f32 "
        "{%0,%1,%2,%3}, {%4,%5,%6,%7}, {%8,%9}, {%0,%1,%2,%3};"
        : "+f"(d[0]), "+f"(d[1]), "+f"(d[2]), "+f"(d[3])
        : "r"(a0), "r"(a1), "r"(a2), "r"(a3), "r"(b0), "r"(b1));
}
// group swizzle keyed on row (bit0 -> group bit2; bits1-2 -> group bits0-1)
__device__ __forceinline__ int swz3(int r) { return ((r & 1) << 2) | ((r >> 1) & 3); }

// ---------------- kernel 1: fp16 MMA QKV projection --------------------------
// grid (32 row-tiles, 3 proj); 256 threads = 8 warps; 16 rows per warp.
__global__ __launch_bounds__(256) void proj_kernel(
    const float* __restrict__ x,
    const float* __restrict__ Wq, const float* __restrict__ bq,
    const float* __restrict__ Wk, const float* __restrict__ bk,
    const float* __restrict__ Wv, const float* __restrict__ bv) {

    extern __shared__ uint32_t dsm[];
    uint32_t* sxh = dsm;                 // 128 rows x 64 pair-dwords (swizzled)
    uint32_t* swt = dsm + 128 * 64;      // W^T: 128 n-rows x 64 k-pair dwords
    float*    sb  = (float*)(dsm + 2 * 128 * 64);   // 128 bias

    const int rowbase = blockIdx.x * 128;
    const int proj = blockIdx.y;
    const float* W    = (proj == 0) ? Wq : (proj == 1) ? Wk : Wv;
    const float* bias = (proj == 0) ? bq : (proj == 1) ? bk : bv;
    uint32_t* out     = (proj == 0) ? g_q : (proj == 1) ? g_k : g_v;

    const int tid  = threadIdx.x;
    const int wid  = tid >> 5;
    const int lane = tid & 31;
    const int gid  = lane >> 2;
    const int tig  = lane & 3;

    // ---- fill x (fp32 -> fp16x2 pairs, swizzled) ----
    #pragma unroll 8
    for (int i = 0; i < 32; i++) {
        int e = tid + (i << 8);          // 8192 pairs
        int row = e >> 6, p = e & 63;
        float2 xv = *(const float2*)(x + (size_t)(rowbase + row) * D_IN + 2 * p);
        sxh[row * 64 + ((((p & 7) ^ swz3(row)) << 3) | (p >> 3))] = pack_h2(xv.x, xv.y);
    }
    // ---- fill W^T: swt[n][pair p] = {W[2p][n], W[2p+1][n]} ----
    {
        int n = tid & 127;
        int pbase = (tid >> 7) << 5;
        #pragma unroll 8
        for (int i = 0; i < 32; i++) {
            int p = pbase + i;
            float w0 = W[(size_t)(2 * p)     * HD + n];
            float w1 = W[(size_t)(2 * p + 1) * HD + n];
            swt[n * 64 + ((((p & 7) ^ swz3(n)) << 3) | (p >> 3))] = pack_h2(w0, w1);
        }
    }
    if (tid < 128) sb[tid] = bias[tid];
    __syncthreads();

    // ---- A fragments (rows r0, r1 held for all 16 n-blocks) ----
    const int r0 = (wid << 4) + gid;
    const int r1 = r0 + 8;
    uint32_t a0[8], a1[8], a2[8], a3[8];
    {
        const uint32_t* x0 = &sxh[r0 * 64];
        const uint32_t* x1 = &sxh[r1 * 64];
        int g0 = ((tig)     ^ swz3(r0)) << 3;
        int g2 = ((tig + 4) ^ swz3(r0)) << 3;
        int h0 = ((tig)     ^ swz3(r1)) << 3;
        int h2 = ((tig + 4) ^ swz3(r1)) << 3;
        *(uint4*)&a0[0] = *(const uint4*)&x0[g0]; *(uint4*)&a0[4] = *(const uint4*)&x0[g0 + 4];
        *(uint4*)&a2[0] = *(const uint4*)&x0[g2]; *(uint4*)&a2[4] = *(const uint4*)&x0[g2 + 4];
        *(uint4*)&a1[0] = *(const uint4*)&x1[h0]; *(uint4*)&a1[4] = *(const uint4*)&x1[h0 + 4];
        *(uint4*)&a3[0] = *(const uint4*)&x1[h2]; *(uint4*)&a3[4] = *(const uint4*)&x1[h2 + 4];
    }

    const float oscale = (proj == 0) ? QSCALE : 1.0f;
    const bool permute = (proj != 2);

    // ---- 16 n-blocks, 2 at a time for MMA ILP ----
    #pragma unroll 1
    for (int nb2 = 0; nb2 < 8; nb2++) {
        const int nbA = 2 * nb2, nbB = 2 * nb2 + 1;
        const int nA = nbA * 8 + gid, nB = nbB * 8 + gid;

        uint32_t b0A[8], b1A[8], b0B[8], b1B[8];
        {
            const uint32_t* wA = &swt[nA * 64];
            int ga = ((tig)     ^ swz3(nA)) << 3;
            int gb = ((tig + 4) ^ swz3(nA)) << 3;
            *(uint4*)&b0A[0] = *(const uint4*)&wA[ga]; *(uint4*)&b0A[4] = *(const uint4*)&wA[ga + 4];
            *(uint4*)&b1A[0] = *(const uint4*)&wA[gb]; *(uint4*)&b1A[4] = *(const uint4*)&wA[gb + 4];
            const uint32_t* wB = &swt[nB * 64];
            int gc = ((tig)     ^ swz3(nB)) << 3;
            int gd = ((tig + 4) ^ swz3(nB)) << 3;
            *(uint4*)&b0B[0] = *(const uint4*)&wB[gc]; *(uint4*)&b0B[4] = *(const uint4*)&wB[gc + 4];
            *(uint4*)&b1B[0] = *(const uint4*)&wB[gd]; *(uint4*)&b1B[4] = *(const uint4*)&wB[gd + 4];
        }

        float cA[4] = {0.f, 0.f, 0.f, 0.f};
        float cB[4] = {0.f, 0.f, 0.f, 0.f};
        #pragma unroll
        for (int ks = 0; ks < 8; ks++) {
            mma16(cA, a0[ks], a1[ks], a2[ks], a3[ks], b0A[ks], b1A[ks]);
            mma16(cB, a0[ks], a1[ks], a2[ks], a3[ks], b0B[ks], b1B[ks]);
        }

        // ---- epilogue for both n-blocks ----
        #pragma unroll
        for (int s = 0; s < 2; s++) {
            const float* c = s ? cB : cA;
            const int nb = s ? nbB : nbA;
            const int col0 = 8 * nb + 2 * tig;
            float v0 = (c[0] + sb[col0])     * oscale;   // row r0
            float v1 = (c[1] + sb[col0 + 1]) * oscale;
            float v2 = (c[2] + sb[col0])     * oscale;   // row r1
            float v3 = (c[3] + sb[col0 + 1]) * oscale;
            int h0 = col0 >> 5;
            int d2 = (col0 >> 1) & 15;
            int p  = permute ? (((d2 & 3) << 2) | (d2 >> 2)) : d2;
            out[((size_t)h0 * S + rowbase + r0) * 16 + p] = pack_h2(v0, v1);
            out[((size_t)h0 * S + rowbase + r1) * 16 + p] = pack_h2(v2, v3);
        }
    }
}

// ---------------- kernel 2: fp16 m16n8k16 flash attention -------------------
// grid (16, H, 4) = 256 blocks; 256 threads = 8 warps; 32 queries per warp.
__global__ __launch_bounds__(256, 2) void attn_kernel(const int* __restrict__ mask) {
    const int qtile = blockIdx.x;
    const int h     = blockIdx.y;
    const int kc    = blockIdx.z;
    const int tid   = threadIdx.x;
    const int warp  = tid >> 5;
    const int lane  = tid & 31;
    const int gid   = lane >> 2;
    const int tig   = lane & 3;

    __shared__ __align__(16) uint32_t sk[KT * 16];             // 8 KB (permuted fp16x2)
    __shared__ __align__(16) uint32_t sv[(KT / 16) * V_CHSTR]; // 8.25 KB
    __shared__ float sbias[KT];
    __shared__ int smask[64];

    if (tid < 64) smask[tid] = mask[tid];

    const int qbase = qtile * QT + warp * 32;

    uint4 qlo[2], qhi[2];
    #pragma unroll
    for (int t = 0; t < 2; t++) {
        const uint32_t* qr = g_q + ((size_t)(h * S) + qbase + t * 16 + gid) * 16;
        qlo[t] = *(const uint4*)(qr + 4 * tig);
        qhi[t] = *(const uint4*)(qr + 8 * 16 + 4 * tig);
    }

    float o[2][4][4];
    #pragma unroll
    for (int t = 0; t < 2; t++)
        #pragma unroll
        for (int nc = 0; nc < 4; nc++)
            #pragma unroll
            for (int r = 0; r < 4; r++) o[t][nc][r] = 0.0f;
    float l[2][2] = {{0.f, 0.f}, {0.f, 0.f}};

    const int kbase = kc * KEYS_PER_SPLIT;
    const float2* sb2 = (const float2*)sbias;

    const int vkey2 = tid & 63;
    const int vdb   = tid >> 6;
    const int vch   = vkey2 >> 3;
    const int vkc2  = vkey2 & 7;
    const int vwoff = vch * V_CHSTR + 64 * vdb + 2 * (vkc2 & 3) + (vkc2 >> 2);

    for (int jt = 0; jt < KEYS_PER_SPLIT / KT; jt++) {   // 8 tiles
        __syncthreads();
        {
            const uint4* kg4 = (const uint4*)(g_k + ((size_t)(h * S) + kbase + jt * KT) * 16);
            ((uint4*)sk)[tid]       = kg4[tid];
            ((uint4*)sk)[tid + 256] = kg4[tid + 256];

            const uint4* vg4 = (const uint4*)(g_v + ((size_t)(h * S) + kbase + jt * KT) * 16);
            uint4 e4 = vg4[(2 * vkey2) * 4 + vdb];
            uint4 o4 = vg4[(2 * vkey2) * 4 + 4 + vdb];
            uint32_t* dst = &sv[vwoff];
            dst[0]  = __byte_perm(e4.x, o4.x, 0x5410);
            dst[8]  = __byte_perm(e4.x, o4.x, 0x7632);
            dst[16] = __byte_perm(e4.y, o4.y, 0x5410);
            dst[24] = __byte_perm(e4.y, o4.y, 0x7632);
            dst[32] = __byte_perm(e4.z, o4.z, 0x5410);
            dst[40] = __byte_perm(e4.z, o4.z, 0x7632);
            dst[48] = __byte_perm(e4.w, o4.w, 0x5410);
            dst[56] = __byte_perm(e4.w, o4.w, 0x7632);

            if (tid < KT) {
                int key = kbase + jt * KT + tid;
                sbias[tid] = (smask[key >> 6] && smask[key & 63]) ? 0.0f : -NEGBIG;
            }
        }
        __syncthreads();

        #pragma unroll 1
        for (int kg = 0; kg < KT / 16; kg++) {     // 8 chunks of 16 keys
            const uint4 kb0 = *(const uint4*)&sk[(kg * 16 + gid) * 16 + 4 * tig];
            const uint4 kb1 = *(const uint4*)&sk[(kg * 16 + 8 + gid) * 16 + 4 * tig];

            float c[2][2][4];
            #pragma unroll
            for (int t = 0; t < 2; t++) {
                #pragma unroll
                for (int g = 0; g < 2; g++)
                    c[t][g][0] = c[t][g][1] = c[t][g][2] = c[t][g][3] = 0.0f;
                mma16(c[t][0], qlo[t].x, qhi[t].x, qlo[t].y, qhi[t].y, kb0.x, kb0.y);
                mma16(c[t][0], qlo[t].z, qhi[t].z, qlo[t].w, qhi[t].w, kb0.z, kb0.w);
                mma16(c[t][1], qlo[t].x, qhi[t].x, qlo[t].y, qhi[t].y, kb1.x, kb1.y);
                mma16(c[t][1], qlo[t].z, qhi[t].z, qlo[t].w, qhi[t].w, kb1.z, kb1.w);
            }

            float2 bg0 = sb2[kg * 8 + tig];
            float2 bg1 = sb2[kg * 8 + 4 + tig];

            uint32_t pa[2][4];
            #pragma unroll
            for (int t = 0; t < 2; t++) {
                float p00 = ex2(c[t][0][0] + bg0.x), p01 = ex2(c[t][0][1] + bg0.y);
                float p02 = ex2(c[t][0][2] + bg0.x), p03 = ex2(c[t][0][3] + bg0.y);
                float p10 = ex2(c[t][1][0] + bg1.x), p11 = ex2(c[t][1][1] + bg1.y);
                float p12 = ex2(c[t][1][2] + bg1.x), p13 = ex2(c[t][1][3] + bg1.y);
                l[t][0] += (p00 + p01) + (p10 + p11);
                l[t][1] += (p02 + p03) + (p12 + p13);
                pa[t][0] = pack_h2(p00, p01);
                pa[t][1] = pack_h2(p02, p03);
                pa[t][2] = pack_h2(p10, p11);
                pa[t][3] = pack_h2(p12, p13);
            }

            const uint32_t* vb = &sv[kg * V_CHSTR + 8 * gid + 2 * tig];
            #pragma unroll
            for (int nc = 0; nc < 4; nc++) {
                uint2 vv = *(const uint2*)(vb + 64 * nc);
                mma16(o[0][nc], pa[0][0], pa[0][1], pa[0][2], pa[0][3], vv.x, vv.y);
                mma16(o[1][nc], pa[1][0], pa[1][1], pa[1][2], pa[1][3], vv.x, vv.y);
            }
        }
    }

    // ---- reduce l within groups; write partials ----
    const unsigned FULL = 0xffffffffu;
    #pragma unroll
    for (int t = 0; t < 2; t++) {
        float l0 = l[t][0], l1 = l[t][1];
        l0 += __shfl_xor_sync(FULL, l0, 1); l0 += __shfl_xor_sync(FULL, l0, 2);
        l1 += __shfl_xor_sync(FULL, l1, 1); l1 += __shfl_xor_sync(FULL, l1, 2);

        const int q0 = qbase + t * 16 + gid;
        const int q1 = q0 + 8;
        const int prow0 = ((h * S) + q0) * KSPLIT + kc;
        const int prow1 = ((h * S) + q1) * KSPLIT + kc;
        if (tig == 0) { g_pl[prow0] = l0; g_pl[prow1] = l1; }

        float2* po0 = (float2*)(g_po + (size_t)prow0 * D);
        float2* po1 = (float2*)(g_po + (size_t)prow1 * D);
        #pragma unroll
        for (int nc = 0; nc < 4; nc++) {
            po0[nc * 4 + tig] = make_float2(o[t][nc][0], o[t][nc][1]);
            po1[nc * 4 + tig] = make_float2(o[t][nc][2], o[t][nc][3]);
        }
    }
}

// ---------------- kernel 3: combine split-K + sum-pool over j ---------------
// Identical structure to R9's version; only change: full unroll of the jj loop
// to maximize loads in flight (MLP 16 -> ~64).
__global__ __launch_bounds__(128) void reduce_kernel(float* __restrict__ out) {
    const int i = blockIdx.x;
    const int h = blockIdx.y;
    const int tid = threadIdx.x;
    const int jg = tid >> 5;
    const int d  = tid & 31;

    __shared__ float sinvL[64];
    __shared__ float sacc[128];

    if (tid < 64) {
        int s = i * 64 + tid;
        int base = (h * S + s) * KSPLIT;
        float L = 0.0f;
        #pragma unroll
        for (int k = 0; k < KSPLIT; k++) L += g_pl[base + k];
        sinvL[tid] = 1.0f / L;
    }
    __syncthreads();

    float acc = 0.0f;
    #pragma unroll
    for (int jj = 0; jj < 16; jj++) {
        int j = jg * 16 + jj;
        int s = i * 64 + j;
        size_t base = ((size_t)(h * S + s) * KSPLIT) * D + d;
        float ov = 0.0f;
        #pragma unroll
        for (int k = 0; k < KSPLIT; k++) ov += g_po[base + (size_t)k * D];
        acc += ov * sinvL[j];
    }

    sacc[tid] = acc;
    __syncthreads();
    if (tid < 32) {
        float r = sacc[tid] + sacc[tid + 32] + sacc[tid + 64] + sacc[tid + 96];
        out[i * HD + h * 32 + tid] = r;
    }
}

// ---------------- launch ----------------------------------------------------
extern "C" void kernel_launch(void* const* d_in, const int* in_sizes, int n_in,
                              void* d_out, int out_size) {
    const float* x    = (const float*)d_in[0];
    const int*   mask = (const int*)  d_in[1];
    const float* Wq   = (const float*)d_in[2];
    const float* bq   = (const float*)d_in[3];
    const float* Wk   = (const float*)d_in[4];
    const float* bk   = (const float*)d_in[5];
    const float* Wv   = (const float*)d_in[6];
    const float* bv   = (const float*)d_in[7];
    float* out = (float*)d_out;

    cudaFuncSetAttribute(proj_kernel, cudaFuncAttributeMaxDynamicSharedMemorySize, PROJ_SMEM);
    proj_kernel<<<dim3(S / 128, 3), 256, PROJ_SMEM>>>(x, Wq, bq, Wk, bk, Wv, bv);
    attn_kernel<<<dim3(S / QT, H, KSPLIT), 256>>>(mask);
    reduce_kernel<<<dim3(64, H), 128>>>(out);
}

// round 13
// speedup vs baseline: 1.5142x; 1.0179x over previous
#include <cuda_runtime.h>
#include <cuda_fp16.h>
#include <cstdint>

#define S        4096
#define D_IN     128
#define H        4
#define D        32
#define HD       128
#define KSPLIT   4
#define KEYS_PER_SPLIT (S / KSPLIT)   // 1024
#define KT       128                   // keys per smem tile
#define QT       256                   // queries per attention block (8 warps * 32)
#define NEGBIG   1e30f
#define QSCALE   (0.17677669529663687f * 1.4426950408889634f)  // scale*log2e

#define V_CHSTR  264                   // dwords per 16-key V chunk (256 + 8 pad)

// ---------------- scratch (fp16x2 packed) ------------------------------------
__device__ uint32_t g_q[H * S * 16];        // permuted cols, pre-scaled by QSCALE
__device__ uint32_t g_k[H * S * 16];        // permuted cols
__device__ uint32_t g_v[H * S * 16];        // plain d-pair packing
__device__ uint32_t g_xf[S * 64];           // x packed, A-fragment order
__device__ uint32_t g_wt[3 * 128 * 64];     // W^T packed, swizzled smem image
__device__ float g_pl[H * S * KSPLIT];
__device__ float g_po[H * S * KSPLIT * D];

// ---------------- helpers ----------------------------------------------------
__device__ __forceinline__ float ex2(float x) {
    float r;
    asm("ex2.approx.f32 %0, %1;" : "=f"(r) : "f"(x));
    return r;
}
__device__ __forceinline__ uint32_t pack_h2(float lo, float hi) {
    __half2 h = __floats2half2_rn(lo, hi);       // x = lo bits, y = hi bits
    return *reinterpret_cast<uint32_t*>(&h);
}
__device__ __forceinline__ void mma16(float* d,
                                      uint32_t a0, uint32_t a1, uint32_t a2, uint32_t a3,
                                      uint32_t b0, uint32_t b1) {
    asm("mma.sync.aligned.m16n8k16.row.col.f32.f16.f16.f32 "
        "{%0,%1,%2,%3}, {%4,%5,%6,%7}, {%8,%9}, {%0,%1,%2,%3};"
        : "+f"(d[0]), "+f"(d[1]), "+f"(d[2]), "+f"(d[3])
        : "r"(a0), "r"(a1), "r"(a2), "r"(a3), "r"(b0), "r"(b1));
}
// group swizzle keyed on row (bit0 -> group bit2; bits1-2 -> group bits0-1)
__device__ __forceinline__ int swz3(int r) { return ((r & 1) << 2) | ((r >> 1) & 3); }

// ---------------- kernel 0: prep (pack x in A-frag order; pack W^T) ----------
// grid 304: blocks 0..255 pack x (4 pairs/thread); 256..303 pack W (2 pairs/thread).
__global__ __launch_bounds__(256) void prep_kernel(
    const float* __restrict__ x,
    const float* __restrict__ Wq, const float* __restrict__ Wk,
    const float* __restrict__ Wv) {
    const int bid = blockIdx.x;
    const int tid = threadIdx.x;
    if (bid < 256) {
        const int base = (bid * 256 + tid) * 4;
        #pragma unroll
        for (int i = 0; i < 4; i++) {
            int e = base + i;                 // pair index 0..262143
            int row = e >> 6, p = e & 63;
            float2 xv = *(const float2*)(x + (size_t)row * D_IN + 2 * p);
            // A-frag order: dword = (p&7)*8 + (p>>3)  (t*8 + ks)
            g_xf[row * 64 + ((p & 7) << 3) + (p >> 3)] = pack_h2(xv.x, xv.y);
        }
    } else {
        const int b = bid - 256;              // 0..47
        const int proj = b >> 4, chunk = b & 15;
        const float* W = (proj == 0) ? Wq : (proj == 1) ? Wk : Wv;
        uint32_t* out = g_wt + proj * 8192;
        #pragma unroll
        for (int i = 0; i < 2; i++) {
            int e = chunk * 512 + i * 256 + tid;   // 0..8191, n-fast for coalescing
            int n = e & 127, p = e >> 7;           // p 0..63 over the 16 chunks*2
            // note: e covers p = (chunk*512+..)>>7: chunk contributes 4 p values
            float w0 = W[(size_t)(2 * p) * HD + n];
            float w1 = W[(size_t)(2 * p + 1) * HD + n];
            out[n * 64 + ((((p & 7) ^ swz3(n)) << 3) | (p >> 3))] = pack_h2(w0, w1);
        }
    }
}

// ---------------- kernel 1: fp16 MMA QKV projection (prepped inputs) ---------
// grid (64 row-tiles of 64 rows, 3 proj) = 192 blocks; 256 threads = 8 warps.
// Warp (nh = wid>>2, rh = wid&3): rows rh*16..+15, n-blocks nh*8..nh*8+7.
__global__ __launch_bounds__(256) void proj_kernel(
    const float* __restrict__ bq, const float* __restrict__ bk,
    const float* __restrict__ bv) {

    __shared__ __align__(16) uint32_t swt[8192];   // 32 KB W^T image
    __shared__ float sb[128];

    const int rowbase = blockIdx.x * 64;
    const int proj = blockIdx.y;
    const float* bias = (proj == 0) ? bq : (proj == 1) ? bk : bv;
    uint32_t* out     = (proj == 0) ? g_q : (proj == 1) ? g_k : g_v;

    const int tid  = threadIdx.x;
    const int wid  = tid >> 5;
    const int lane = tid & 31;
    const int gid  = lane >> 2;
    const int tig  = lane & 3;
    const int nh   = wid >> 2;
    const int rh   = wid & 3;

    // ---- linear copy of prepped W^T ----
    {
        const uint4* src = (const uint4*)(g_wt + proj * 8192);
        uint4* dst = (uint4*)swt;
        #pragma unroll
        for (int i = 0; i < 8; i++) dst[tid + i * 256] = src[tid + i * 256];
    }
    if (tid < 128) sb[tid] = bias[tid];

    // ---- A fragments straight from prepped gmem (no smem, no cvt) ----
    const int r0 = rowbase + rh * 16 + gid;
    const int r1 = r0 + 8;
    uint32_t a0[8], a1[8], a2[8], a3[8];
    {
        const uint32_t* x0 = g_xf + (size_t)r0 * 64;
        const uint32_t* x1 = g_xf + (size_t)r1 * 64;
        *(uint4*)&a0[0] = *(const uint4*)&x0[tig * 8];
        *(uint4*)&a0[4] = *(const uint4*)&x0[tig * 8 + 4];
        *(uint4*)&a2[0] = *(const uint4*)&x0[(tig + 4) * 8];
        *(uint4*)&a2[4] = *(const uint4*)&x0[(tig + 4) * 8 + 4];
        *(uint4*)&a1[0] = *(const uint4*)&x1[tig * 8];
        *(uint4*)&a1[4] = *(const uint4*)&x1[tig * 8 + 4];
        *(uint4*)&a3[0] = *(const uint4*)&x1[(tig + 4) * 8];
        *(uint4*)&a3[4] = *(const uint4*)&x1[(tig + 4) * 8 + 4];
    }
    __syncthreads();

    const float oscale = (proj == 0) ? QSCALE : 1.0f;
    const bool permute = (proj != 2);

    // ---- 8 n-blocks for this warp's half, 2 at a time for MMA ILP ----
    #pragma unroll 1
    for (int nb2 = 0; nb2 < 4; nb2++) {
        const int nbA = nh * 8 + 2 * nb2, nbB = nbA + 1;
        const int nA = nbA * 8 + gid, nB = nbB * 8 + gid;

        uint32_t b0A[8], b1A[8], b0B[8], b1B[8];
        {
            const uint32_t* wA = &swt[nA * 64];
            int ga = ((tig)     ^ swz3(nA)) << 3;
            int gb = ((tig + 4) ^ swz3(nA)) << 3;
            *(uint4*)&b0A[0] = *(const uint4*)&wA[ga]; *(uint4*)&b0A[4] = *(const uint4*)&wA[ga + 4];
            *(uint4*)&b1A[0] = *(const uint4*)&wA[gb]; *(uint4*)&b1A[4] = *(const uint4*)&wA[gb + 4];
            const uint32_t* wB = &swt[nB * 64];
            int gc = ((tig)     ^ swz3(nB)) << 3;
            int gd = ((tig + 4) ^ swz3(nB)) << 3;
            *(uint4*)&b0B[0] = *(const uint4*)&wB[gc]; *(uint4*)&b0B[4] = *(const uint4*)&wB[gc + 4];
            *(uint4*)&b1B[0] = *(const uint4*)&wB[gd]; *(uint4*)&b1B[4] = *(const uint4*)&wB[gd + 4];
        }

        float cA[4] = {0.f, 0.f, 0.f, 0.f};
        float cB[4] = {0.f, 0.f, 0.f, 0.f};
        #pragma unroll
        for (int ks = 0; ks < 8; ks++) {
            mma16(cA, a0[ks], a1[ks], a2[ks], a3[ks], b0A[ks], b1A[ks]);
            mma16(cB, a0[ks], a1[ks], a2[ks], a3[ks], b0B[ks], b1B[ks]);
        }

        // ---- epilogue for both n-blocks ----
        #pragma unroll
        for (int s = 0; s < 2; s++) {
            const float* c = s ? cB : cA;
            const int nb = s ? nbB : nbA;
            const int col0 = 8 * nb + 2 * tig;
            float v0 = (c[0] + sb[col0])     * oscale;   // row r0
            float v1 = (c[1] + sb[col0 + 1]) * oscale;
            float v2 = (c[2] + sb[col0])     * oscale;   // row r1
            float v3 = (c[3] + sb[col0 + 1]) * oscale;
            int h0 = col0 >> 5;
            int d2 = (col0 >> 1) & 15;
            int p  = permute ? (((d2 & 3) << 2) | (d2 >> 2)) : d2;
            out[((size_t)h0 * S + r0) * 16 + p] = pack_h2(v0, v1);
            out[((size_t)h0 * S + r1) * 16 + p] = pack_h2(v2, v3);
        }
    }
}

// ---------------- kernel 2: fp16 m16n8k16 flash attention -------------------
// grid (16, H, 4) = 256 blocks; 256 threads = 8 warps; 32 queries per warp.
__global__ __launch_bounds__(256, 2) void attn_kernel(const int* __restrict__ mask) {
    const int qtile = blockIdx.x;
    const int h     = blockIdx.y;
    const int kc    = blockIdx.z;
    const int tid   = threadIdx.x;
    const int warp  = tid >> 5;
    const int lane  = tid & 31;
    const int gid   = lane >> 2;
    const int tig   = lane & 3;

    __shared__ __align__(16) uint32_t sk[KT * 16];             // 8 KB (permuted fp16x2)
    __shared__ __align__(16) uint32_t sv[(KT / 16) * V_CHSTR]; // 8.25 KB
    __shared__ float sbias[KT];
    __shared__ int smask[64];

    if (tid < 64) smask[tid] = mask[tid];

    const int qbase = qtile * QT + warp * 32;

    uint4 qlo[2], qhi[2];
    #pragma unroll
    for (int t = 0; t < 2; t++) {
        const uint32_t* qr = g_q + ((size_t)(h * S) + qbase + t * 16 + gid) * 16;
        qlo[t] = *(const uint4*)(qr + 4 * tig);
        qhi[t] = *(const uint4*)(qr + 8 * 16 + 4 * tig);
    }

    float o[2][4][4];
    #pragma unroll
    for (int t = 0; t < 2; t++)
        #pragma unroll
        for (int nc = 0; nc < 4; nc++)
            #pragma unroll
            for (int r = 0; r < 4; r++) o[t][nc][r] = 0.0f;
    float l[2][2] = {{0.f, 0.f}, {0.f, 0.f}};

    const int kbase = kc * KEYS_PER_SPLIT;
    const float2* sb2 = (const float2*)sbias;

    const int vkey2 = tid & 63;
    const int vdb   = tid >> 6;
    const int vch   = vkey2 >> 3;
    const int vkc2  = vkey2 & 7;
    const int vwoff = vch * V_CHSTR + 64 * vdb + 2 * (vkc2 & 3) + (vkc2 >> 2);

    for (int jt = 0; jt < KEYS_PER_SPLIT / KT; jt++) {   // 8 tiles
        __syncthreads();
        {
            const uint4* kg4 = (const uint4*)(g_k + ((size_t)(h * S) + kbase + jt * KT) * 16);
            ((uint4*)sk)[tid]       = kg4[tid];
            ((uint4*)sk)[tid + 256] = kg4[tid + 256];

            const uint4* vg4 = (const uint4*)(g_v + ((size_t)(h * S) + kbase + jt * KT) * 16);
            uint4 e4 = vg4[(2 * vkey2) * 4 + vdb];
            uint4 o4 = vg4[(2 * vkey2) * 4 + 4 + vdb];
            uint32_t* dst = &sv[vwoff];
            dst[0]  = __byte_perm(e4.x, o4.x, 0x5410);
            dst[8]  = __byte_perm(e4.x, o4.x, 0x7632);
            dst[16] = __byte_perm(e4.y, o4.y, 0x5410);
            dst[24] = __byte_perm(e4.y, o4.y, 0x7632);
            dst[32] = __byte_perm(e4.z, o4.z, 0x5410);
            dst[40] = __byte_perm(e4.z, o4.z, 0x7632);
            dst[48] = __byte_perm(e4.w, o4.w, 0x5410);
            dst[56] = __byte_perm(e4.w, o4.w, 0x7632);

            if (tid < KT) {
                int key = kbase + jt * KT + tid;
                sbias[tid] = (smask[key >> 6] && smask[key & 63]) ? 0.0f : -NEGBIG;
            }
        }
        __syncthreads();

        #pragma unroll 1
        for (int kg = 0; kg < KT / 16; kg++) {     // 8 chunks of 16 keys
            const uint4 kb0 = *(const uint4*)&sk[(kg * 16 + gid) * 16 + 4 * tig];
            const uint4 kb1 = *(const uint4*)&sk[(kg * 16 + 8 + gid) * 16 + 4 * tig];

            float c[2][2][4];
            #pragma unroll
            for (int t = 0; t < 2; t++) {
                #pragma unroll
                for (int g = 0; g < 2; g++)
                    c[t][g][0] = c[t][g][1] = c[t][g][2] = c[t][g][3] = 0.0f;
                mma16(c[t][0], qlo[t].x, qhi[t].x, qlo[t].y, qhi[t].y, kb0.x, kb0.y);
                mma16(c[t][0], qlo[t].z, qhi[t].z, qlo[t].w, qhi[t].w, kb0.z, kb0.w);
                mma16(c[t][1], qlo[t].x, qhi[t].x, qlo[t].y, qhi[t].y, kb1.x, kb1.y);
                mma16(c[t][1], qlo[t].z, qhi[t].z, qlo[t].w, qhi[t].w, kb1.z, kb1.w);
            }

            float2 bg0 = sb2[kg * 8 + tig];
            float2 bg1 = sb2[kg * 8 + 4 + tig];

            uint32_t pa[2][4];
            #pragma unroll
            for (int t = 0; t < 2; t++) {
                float p00 = ex2(c[t][0][0] + bg0.x), p01 = ex2(c[t][0][1] + bg0.y);
                float p02 = ex2(c[t][0][2] + bg0.x), p03 = ex2(c[t][0][3] + bg0.y);
                float p10 = ex2(c[t][1][0] + bg1.x), p11 = ex2(c[t][1][1] + bg1.y);
                float p12 = ex2(c[t][1][2] + bg1.x), p13 = ex2(c[t][1][3] + bg1.y);
                l[t][0] += (p00 + p01) + (p10 + p11);
                l[t][1] += (p02 + p03) + (p12 + p13);
                pa[t][0] = pack_h2(p00, p01);
                pa[t][1] = pack_h2(p02, p03);
                pa[t][2] = pack_h2(p10, p11);
                pa[t][3] = pack_h2(p12, p13);
            }

            const uint32_t* vb = &sv[kg * V_CHSTR + 8 * gid + 2 * tig];
            #pragma unroll
            for (int nc = 0; nc < 4; nc++) {
                uint2 vv = *(const uint2*)(vb + 64 * nc);
                mma16(o[0][nc], pa[0][0], pa[0][1], pa[0][2], pa[0][3], vv.x, vv.y);
                mma16(o[1][nc], pa[1][0], pa[1][1], pa[1][2], pa[1][3], vv.x, vv.y);
            }
        }
    }

    // ---- reduce l within groups; write partials ----
    const unsigned FULL = 0xffffffffu;
    #pragma unroll
    for (int t = 0; t < 2; t++) {
        float l0 = l[t][0], l1 = l[t][1];
        l0 += __shfl_xor_sync(FULL, l0, 1); l0 += __shfl_xor_sync(FULL, l0, 2);
        l1 += __shfl_xor_sync(FULL, l1, 1); l1 += __shfl_xor_sync(FULL, l1, 2);

        const int q0 = qbase + t * 16 + gid;
        const int q1 = q0 + 8;
        const int prow0 = ((h * S) + q0) * KSPLIT + kc;
        const int prow1 = ((h * S) + q1) * KSPLIT + kc;
        if (tig == 0) { g_pl[prow0] = l0; g_pl[prow1] = l1; }

        float2* po0 = (float2*)(g_po + (size_t)prow0 * D);
        float2* po1 = (float2*)(g_po + (size_t)prow1 * D);
        #pragma unroll
        for (int nc = 0; nc < 4; nc++) {
            po0[nc * 4 + tig] = make_float2(o[t][nc][0], o[t][nc][1]);
            po1[nc * 4 + tig] = make_float2(o[t][nc][2], o[t][nc][3]);
        }
    }
}

// ---------------- kernel 3: combine split-K + sum-pool over j ---------------
__global__ __launch_bounds__(128) void reduce_kernel(float* __restrict__ out) {
    const int i = blockIdx.x;
    const int h = blockIdx.y;
    const int tid = threadIdx.x;
    const int jg = tid >> 5;
    const int d  = tid & 31;

    __shared__ float sinvL[64];
    __shared__ float sacc[128];

    if (tid < 64) {
        int s = i * 64 + tid;
        int base = (h * S + s) * KSPLIT;
        float L = 0.0f;
        #pragma unroll
        for (int k = 0; k < KSPLIT; k++) L += g_pl[base + k];
        sinvL[tid] = 1.0f / L;
    }
    __syncthreads();

    float acc = 0.0f;
    #pragma unroll
    for (int jj = 0; jj < 16; jj++) {
        int j = jg * 16 + jj;
        int s = i * 64 + j;
        size_t base = ((size_t)(h * S + s) * KSPLIT) * D + d;
        float ov = 0.0f;
        #pragma unroll
        for (int k = 0; k < KSPLIT; k++) ov += g_po[base + (size_t)k * D];
        acc += ov * sinvL[j];
    }

    sacc[tid] = acc;
    __syncthreads();
    if (tid < 32) {
        float r = sacc[tid] + sacc[tid + 32] + sacc[tid + 64] + sacc[tid + 96];
        out[i * HD + h * 32 + tid] = r;
    }
}

// ---------------- launch ----------------------------------------------------
extern "C" void kernel_launch(void* const* d_in, const int* in_sizes, int n_in,
                              void* d_out, int out_size) {
    const float* x    = (const float*)d_in[0];
    const int*   mask = (const int*)  d_in[1];
    const float* Wq   = (const float*)d_in[2];
    const float* bq   = (const float*)d_in[3];
    const float* Wk   = (const float*)d_in[4];
    const float* bk   = (const float*)d_in[5];
    const float* Wv   = (const float*)d_in[6];
    const float* bv   = (const float*)d_in[7];
    float* out = (float*)d_out;

    prep_kernel<<<304, 256>>>(x, Wq, Wk, Wv);
    proj_kernel<<<dim3(S / 64, 3), 256>>>(bq, bk, bv);
    attn_kernel<<<dim3(S / QT, H, KSPLIT), 256>>>(mask);
    reduce_kernel<<<dim3(64, H), 128>>>(out);
}